// round 10
// baseline (speedup 1.0000x reference)
#include <cuda_runtime.h>
#include <cuda_bf16.h>

// ---------------------------------------------------------------------------
// NDCG loss, N = 16,777,216 (general N supported up to MAXG*EPB).
// Pass 1: score -> per-32-elem bitmask + per-block positive counts.
//         ALL 32 scalar loads issued before ballots (32 lines in flight/warp).
// Pass 2: predict + bitmask -> unified branch-free term, float-tracked ranks.
//         ALL 8 float4 loads issued before compute (32 lines in flight/warp).
// Pass 3: deterministic reduction of partials -> d_out[0].
// ---------------------------------------------------------------------------

#define EPB 8192            // elements per block (256 thr * 32 elem)
#define EPW 1024            // elements per warp
#define MAXG 4096           // max blocks supported by static scratch

__device__ unsigned int g_mask[MAXG * 256];   // 1 bit per element
__device__ int          g_counts[MAXG];       // positives per block
__device__ float        g_partials[MAXG];     // per-block loss partials

// ---------------------------------------------------------------------------
__global__ __launch_bounds__(256, 4) void k_mask(const float* __restrict__ score,
                                                 int N) {
    const int warp = threadIdx.x >> 5, lane = threadIdx.x & 31;
    const int base = blockIdx.x * EPB + warp * EPW;

    // Warp covers EPW=1024 elements -> 32 mask words; lane L owns word L.
    // Issue ALL 32 coalesced scalar loads first: 32 x 128B lines in flight.
    float v[32];
    #pragma unroll
    for (int t = 0; t < 32; ++t) {
        int idx = base + t * 32 + lane;
        v[t] = (idx < N) ? __ldcs(score + idx) : 0.0f;
    }

    unsigned myword = 0;
    #pragma unroll
    for (int t = 0; t < 32; ++t) {
        unsigned b = __ballot_sync(0xffffffffu, v[t] > 0.0f);
        if (lane == t) myword = b;
    }
    g_mask[(blockIdx.x << 8) + (warp << 5) + lane] = myword;

    int c = __popc(myword);
    #pragma unroll
    for (int o = 16; o; o >>= 1) c += __shfl_xor_sync(0xffffffffu, c, o);

    __shared__ int sc[8];
    if (lane == 0) sc[warp] = c;
    __syncthreads();
    if (threadIdx.x == 0) {
        int t = 0;
        #pragma unroll
        for (int w = 0; w < 8; ++w) t += sc[w];
        g_counts[blockIdx.x] = t;
    }
}

// ---------------------------------------------------------------------------
__global__ __launch_bounds__(256, 4) void k_loss(const float* __restrict__ pred,
                                                 int N, int G) {
    const int tid  = threadIdx.x;
    const int warp = tid >> 5, lane = tid & 31;

    // --- exclusive block prefix of positives + total P (L2-hot counts) ---
    int pre = 0, tot = 0;
    for (int i = tid; i < G; i += 256) {
        int c = g_counts[i];
        tot += c;
        pre += (i < (int)blockIdx.x) ? c : 0;
    }
    #pragma unroll
    for (int o = 16; o; o >>= 1) {
        pre += __shfl_xor_sync(0xffffffffu, pre, o);
        tot += __shfl_xor_sync(0xffffffffu, tot, o);
    }
    __shared__ int spre[8], stot[8], wsum[8];
    if (lane == 0) { spre[warp] = pre; stot[warp] = tot; }
    __syncthreads();
    int blockPre = 0, P = 0;
    #pragma unroll
    for (int w = 0; w < 8; ++w) { blockPre += spre[w]; P += stot[w]; }

    // --- per-warp mask words + intra-warp positive prefix via popc scan ---
    const int base = blockIdx.x * EPB + warp * EPW;
    unsigned myword = g_mask[(blockIdx.x << 8) + (warp << 5) + lane];
    int wc  = __popc(myword);
    int inc = wc;
    #pragma unroll
    for (int o = 1; o < 32; o <<= 1) {
        int t = __shfl_up_sync(0xffffffffu, inc, o);
        if (lane >= o) inc += t;
    }
    int exc = inc - wc;                 // positives before word 'lane' in warp
    if (lane == 31) wsum[warp] = inc;   // warp total
    __syncthreads();
    int warpBase = blockPre;
    for (int w = 0; w < warp; ++w) warpBase += wsum[w];

    const float Pf    = (float)P;
    const float invP  = 1.0f / Pf;          // s value at positives
    const float sum_s = Pf * invP;          // ~= 1.0 (faithful to reference)
    const float rp    = 1.0f / sum_s;
    const float basef = (float)base;        // hoisted I2F
    const float lane4f = (float)(lane * 4);

    float acc = 0.0f;

    // ---- issue ALL 8 float4 loads first: 32 x 128B lines in flight/warp ----
    float4 pv[8];
    #pragma unroll
    for (int t = 0; t < 8; ++t) {
        int e0 = base + t * 128 + lane * 4;
        if (e0 + 3 < N) {
            pv[t] = __ldcs(reinterpret_cast<const float4*>(pred + e0));
        } else {
            pv[t].x = (e0     < N) ? pred[e0]     : 0.0f;
            pv[t].y = (e0 + 1 < N) ? pred[e0 + 1] : 0.0f;
            pv[t].z = (e0 + 2 < N) ? pred[e0 + 2] : 0.0f;
            pv[t].w = (e0 + 3 < N) ? pred[e0 + 3] : 0.0f;
        }
    }

    // ---- compute 8 quads ----
    #pragma unroll
    for (int j = 0; j < 8; ++j) {
        const int e0 = base + j * 128 + lane * 4;
        const int wl = j * 4 + (lane >> 3);      // word covering these elems
        const unsigned w = __shfl_sync(0xffffffffu, myword, wl);
        const int pe     = __shfl_sync(0xffffffffu, exc,    wl);
        const int bit0   = (lane & 7) * 4;
        const int kbase  = warpBase + pe + __popc(w & ((1u << bit0) - 1u));
        const float pvals[4] = {pv[j].x, pv[j].y, pv[j].z, pv[j].w};

        // Float-tracked ranks: one I2F per quad.
        float kbf = (float)kbase;                 // exclusive positive cnt
        // Pbase_c = P + idx(c) + 2 where idx(c) = e0 + c
        const float Pb0 = Pf + basef + (float)(j * 128) + lane4f + 2.0f;

        #pragma unroll
        for (int c = 0; c < 4; ++c) {
            const int idx = e0 + c;
            const bool pos = (w >> (bit0 + c)) & 1u;
            const float posf = pos ? 1.0f : 0.0f;
            const float p = pvals[c] * rp;
            // pos: A = k+1 = kbf+2 (inclusive), C = log2(A), sel = invP
            //      d = (p*C - invP*A)/(A*C) = p/(k+1) - invP/log2(k+1)
            // neg: A = P+m+1 = (P+idx+2) - kbf, C = 1, sel = 0 -> d = p/A
            const float A   = pos ? (kbf + 2.0f)
                                  : ((Pb0 + (float)c) - kbf);
            const float C   = pos ? __log2f(A) : 1.0f;
            const float sel = pos ? invP : 0.0f;
            const float num = p * C - sel * A;
            const float d   = __fdividef(num, A * C);
            if (idx < N) acc += d * d;
            kbf += posf;
        }
    }

    #pragma unroll
    for (int o = 16; o; o >>= 1) acc += __shfl_xor_sync(0xffffffffu, acc, o);
    __shared__ float sacc[8];
    if (lane == 0) sacc[warp] = acc;
    __syncthreads();
    if (tid == 0) {
        float t = 0.0f;
        #pragma unroll
        for (int w = 0; w < 8; ++w) t += sacc[w];
        g_partials[blockIdx.x] = t;
    }
}

// ---------------------------------------------------------------------------
__global__ __launch_bounds__(256) void k_final(float* __restrict__ out, int G) {
    int tid = threadIdx.x;
    float a = 0.0f;
    for (int i = tid; i < G; i += 256) a += g_partials[i];
    #pragma unroll
    for (int o = 16; o; o >>= 1) a += __shfl_xor_sync(0xffffffffu, a, o);
    __shared__ float s[8];
    if ((tid & 31) == 0) s[tid >> 5] = a;
    __syncthreads();
    if (tid == 0) {
        float t = 0.0f;
        #pragma unroll
        for (int w = 0; w < 8; ++w) t += s[w];
        out[0] = t;
    }
}

// ---------------------------------------------------------------------------
extern "C" void kernel_launch(void* const* d_in, const int* in_sizes, int n_in,
                              void* d_out, int out_size) {
    const float* pred  = (const float*)d_in[0];  // predict_score
    const float* score = (const float*)d_in[1];  // score (0/1)
    int N = in_sizes[0];
    int G = (N + EPB - 1) / EPB;
    if (G > MAXG) G = MAXG;   // problem size is 2^24 -> G = 2048

    k_mask<<<G, 256>>>(score, N);
    k_loss<<<G, 256>>>(pred, N, G);
    k_final<<<1, 256>>>((float*)d_out, G);
}

// round 12
// speedup vs baseline: 1.1595x; 1.1595x over previous
#include <cuda_runtime.h>
#include <cuda_bf16.h>

// ---------------------------------------------------------------------------
// NDCG loss, N = 16,777,216 (general N supported up to MAXG*EPB).
// Pass 1: score --cp.async--> shared tile -> bitmask + per-block counts.
//         (LDGSTS: MLP unconstrained by registers; copy/ballot phases of
//          co-resident blocks overlap on the SM.)
// Pass 2: predict + bitmask -> unified branch-free term, float-tracked ranks.
//         ALL 8 float4 loads issued before compute. (R9, proven 38.9us build)
// Pass 3: deterministic reduction of partials -> d_out[0].
// ---------------------------------------------------------------------------

#define EPB 8192            // elements per block (256 thr * 32 elem)
#define EPW 1024            // elements per warp
#define MAXG 4096           // max blocks supported by static scratch

__device__ unsigned int g_mask[MAXG * 256];   // 1 bit per element
__device__ int          g_counts[MAXG];       // positives per block
__device__ float        g_partials[MAXG];     // per-block loss partials

// ---------------------------------------------------------------------------
__global__ __launch_bounds__(256, 4) void k_mask(const float* __restrict__ score,
                                                 int N) {
    __shared__ float sbuf[EPB];               // 32 KB tile
    const int tid  = threadIdx.x;
    const int warp = tid >> 5, lane = tid & 31;
    const int blkBase = blockIdx.x * EPB;

    if (blkBase + EPB <= N) {
        // Full tile: 8 x 16B cp.async per thread = 2048 chunks in flight.
        #pragma unroll
        for (int t = 0; t < 8; ++t) {
            const int off = t * 1024 + tid * 4;
            unsigned saddr = (unsigned)__cvta_generic_to_shared(sbuf + off);
            const float* g = score + blkBase + off;
            asm volatile("cp.async.cg.shared.global [%0], [%1], 16;\n"
                         :: "r"(saddr), "l"(g));
        }
        asm volatile("cp.async.commit_group;\n");
        asm volatile("cp.async.wait_group 0;\n");
    } else {
        // Tail tile (not hit at N = 2^24): guarded scalar fill.
        for (int i = tid; i < EPB; i += 256) {
            int idx = blkBase + i;
            sbuf[i] = (idx < N) ? score[idx] : 0.0f;
        }
    }
    __syncthreads();

    // Warp covers EPW=1024 elements -> 32 mask words; lane L owns word L.
    unsigned myword = 0;
    #pragma unroll
    for (int t = 0; t < 32; ++t) {
        float v = sbuf[warp * 1024 + t * 32 + lane];
        unsigned b = __ballot_sync(0xffffffffu, v > 0.0f);
        if (lane == t) myword = b;
    }
    g_mask[(blockIdx.x << 8) + (warp << 5) + lane] = myword;

    int c = __popc(myword);
    #pragma unroll
    for (int o = 16; o; o >>= 1) c += __shfl_xor_sync(0xffffffffu, c, o);

    __shared__ int sc[8];
    if (lane == 0) sc[warp] = c;
    __syncthreads();
    if (threadIdx.x == 0) {
        int t = 0;
        #pragma unroll
        for (int w = 0; w < 8; ++w) t += sc[w];
        g_counts[blockIdx.x] = t;
    }
}

// ---------------------------------------------------------------------------
__global__ __launch_bounds__(256, 4) void k_loss(const float* __restrict__ pred,
                                                 int N, int G) {
    const int tid  = threadIdx.x;
    const int warp = tid >> 5, lane = tid & 31;

    // --- exclusive block prefix of positives + total P (L2-hot counts) ---
    int pre = 0, tot = 0;
    for (int i = tid; i < G; i += 256) {
        int c = g_counts[i];
        tot += c;
        pre += (i < (int)blockIdx.x) ? c : 0;
    }
    #pragma unroll
    for (int o = 16; o; o >>= 1) {
        pre += __shfl_xor_sync(0xffffffffu, pre, o);
        tot += __shfl_xor_sync(0xffffffffu, tot, o);
    }
    __shared__ int spre[8], stot[8], wsum[8];
    if (lane == 0) { spre[warp] = pre; stot[warp] = tot; }
    __syncthreads();
    int blockPre = 0, P = 0;
    #pragma unroll
    for (int w = 0; w < 8; ++w) { blockPre += spre[w]; P += stot[w]; }

    // --- per-warp mask words + intra-warp positive prefix via popc scan ---
    const int base = blockIdx.x * EPB + warp * EPW;
    unsigned myword = g_mask[(blockIdx.x << 8) + (warp << 5) + lane];
    int wc  = __popc(myword);
    int inc = wc;
    #pragma unroll
    for (int o = 1; o < 32; o <<= 1) {
        int t = __shfl_up_sync(0xffffffffu, inc, o);
        if (lane >= o) inc += t;
    }
    int exc = inc - wc;                 // positives before word 'lane' in warp
    if (lane == 31) wsum[warp] = inc;   // warp total
    __syncthreads();
    int warpBase = blockPre;
    for (int w = 0; w < warp; ++w) warpBase += wsum[w];

    const float Pf    = (float)P;
    const float invP  = 1.0f / Pf;          // s value at positives
    const float sum_s = Pf * invP;          // ~= 1.0 (faithful to reference)
    const float rp    = 1.0f / sum_s;
    const float basef = (float)base;        // hoisted I2F
    const float lane4f = (float)(lane * 4);

    float acc = 0.0f;

    // ---- issue ALL 8 float4 loads first: 32 x 128B lines in flight/warp ----
    float4 pv[8];
    #pragma unroll
    for (int t = 0; t < 8; ++t) {
        int e0 = base + t * 128 + lane * 4;
        if (e0 + 3 < N) {
            pv[t] = __ldcs(reinterpret_cast<const float4*>(pred + e0));
        } else {
            pv[t].x = (e0     < N) ? pred[e0]     : 0.0f;
            pv[t].y = (e0 + 1 < N) ? pred[e0 + 1] : 0.0f;
            pv[t].z = (e0 + 2 < N) ? pred[e0 + 2] : 0.0f;
            pv[t].w = (e0 + 3 < N) ? pred[e0 + 3] : 0.0f;
        }
    }

    // ---- compute 8 quads ----
    #pragma unroll
    for (int j = 0; j < 8; ++j) {
        const int e0 = base + j * 128 + lane * 4;
        const int wl = j * 4 + (lane >> 3);      // word covering these elems
        const unsigned w = __shfl_sync(0xffffffffu, myword, wl);
        const int pe     = __shfl_sync(0xffffffffu, exc,    wl);
        const int bit0   = (lane & 7) * 4;
        const int kbase  = warpBase + pe + __popc(w & ((1u << bit0) - 1u));
        const float pvals[4] = {pv[j].x, pv[j].y, pv[j].z, pv[j].w};

        // Float-tracked ranks: one I2F per quad.
        float kbf = (float)kbase;                 // exclusive positive cnt
        // Pbase_c = P + idx(c) + 2 where idx(c) = e0 + c
        const float Pb0 = Pf + basef + (float)(j * 128) + lane4f + 2.0f;

        #pragma unroll
        for (int c = 0; c < 4; ++c) {
            const int idx = e0 + c;
            const bool pos = (w >> (bit0 + c)) & 1u;
            const float posf = pos ? 1.0f : 0.0f;
            const float p = pvals[c] * rp;
            // pos: A = k+1 = kbf+2 (inclusive), C = log2(A), sel = invP
            //      d = (p*C - invP*A)/(A*C) = p/(k+1) - invP/log2(k+1)
            // neg: A = P+m+1 = (P+idx+2) - kbf, C = 1, sel = 0 -> d = p/A
            const float A   = pos ? (kbf + 2.0f)
                                  : ((Pb0 + (float)c) - kbf);
            const float C   = pos ? __log2f(A) : 1.0f;
            const float sel = pos ? invP : 0.0f;
            const float num = p * C - sel * A;
            const float d   = __fdividef(num, A * C);
            if (idx < N) acc += d * d;
            kbf += posf;
        }
    }

    #pragma unroll
    for (int o = 16; o; o >>= 1) acc += __shfl_xor_sync(0xffffffffu, acc, o);
    __shared__ float sacc[8];
    if (lane == 0) sacc[warp] = acc;
    __syncthreads();
    if (tid == 0) {
        float t = 0.0f;
        #pragma unroll
        for (int w = 0; w < 8; ++w) t += sacc[w];
        g_partials[blockIdx.x] = t;
    }
}

// ---------------------------------------------------------------------------
__global__ __launch_bounds__(256) void k_final(float* __restrict__ out, int G) {
    int tid = threadIdx.x;
    float a = 0.0f;
    for (int i = tid; i < G; i += 256) a += g_partials[i];
    #pragma unroll
    for (int o = 16; o; o >>= 1) a += __shfl_xor_sync(0xffffffffu, a, o);
    __shared__ float s[8];
    if ((tid & 31) == 0) s[tid >> 5] = a;
    __syncthreads();
    if (tid == 0) {
        float t = 0.0f;
        #pragma unroll
        for (int w = 0; w < 8; ++w) t += s[w];
        out[0] = t;
    }
}

// ---------------------------------------------------------------------------
extern "C" void kernel_launch(void* const* d_in, const int* in_sizes, int n_in,
                              void* d_out, int out_size) {
    const float* pred  = (const float*)d_in[0];  // predict_score
    const float* score = (const float*)d_in[1];  // score (0/1)
    int N = in_sizes[0];
    int G = (N + EPB - 1) / EPB;
    if (G > MAXG) G = MAXG;   // problem size is 2^24 -> G = 2048

    k_mask<<<G, 256>>>(score, N);
    k_loss<<<G, 256>>>(pred, N, G);
    k_final<<<1, 256>>>((float*)d_out, G);
}